// round 6
// baseline (speedup 1.0000x reference)
#include <cuda_runtime.h>

// Time-varying FIR via packed f32x2 FMAs (Blackwell FFMA2).
//   y[t] = sum_k x[t-k]*(bL[n][k] + w*(bR[n][k]-bL[n][k])), n=t/80, w=(t%80)/80
// Two-accumulator split y = A0 + w*A1. Outputs packed in pairs; even/odd tap
// parity handled by two shared x images offset by one float so every 64-bit
// pair load is 8B-aligned.

#define BATCH     8
#define N_FRAMES  3000
#define FPERIOD   80
#define T_LEN     (N_FRAMES * FPERIOD)   // 240000
#define TAPS      50
#define ORD       49

#define FPB       16                     // frames per block (ragged last block)
#define SPB       (FPB * FPERIOD)        // 1280
#define R         8                      // samples per thread (pairs of 2 x 4)
#define TPF       (FPERIOD / R)          // 10 threads per frame
#define THREADS   (FPB * TPF)            // 160 = 5 warps
#define GRIDX     ((N_FRAMES + FPB - 1) / FPB)   // 188

#define SX_LEN    (52 + SPB + 16)        // 1348 floats staged per image

typedef unsigned long long ull;

__device__ __forceinline__ ull fma2(ull a, ull b, ull c) {
    ull d;
    asm("fma.rn.f32x2 %0, %1, %2, %3;" : "=l"(d) : "l"(a), "l"(b), "l"(c));
    return d;
}
__device__ __forceinline__ ull pack2(float lo, float hi) {
    ull d;
    asm("mov.b64 %0, {%1, %2};" : "=l"(d) : "f"(lo), "f"(hi));
    return d;
}
__device__ __forceinline__ ull lds64(const float* p) {
    return *(const ull*)p;               // 8B-aligned by construction
}

__global__ __launch_bounds__(THREADS)
void azdf_kernel(const float* __restrict__ x,
                 const float* __restrict__ b,
                 float* __restrict__ y)
{
    __shared__ __align__(16) float sxA[SX_LEN];      // sxA[i] = x[t0-52+i]
    __shared__ __align__(16) float sxB[SX_LEN];      // sxB[i] = x[t0-51+i]
    __shared__ __align__(16) float sc [FPB * TAPS * 2]; // (c49[j], d49[j]) interleaved

    const int tid = threadIdx.x;
    const int bb  = blockIdx.y;
    const int f0  = blockIdx.x * FPB;
    const int t0  = f0 * FPERIOD;

    const float* xb  = x + (size_t)bb * T_LEN;
    const float* bbp = b + (size_t)bb * N_FRAMES * TAPS;

    // --- stage x (both images), float4 global loads, guarded at edges ---
    const int NV = (SX_LEN + 3) / 4;     // 337 vec4 groups
    for (int i = tid; i < NV; i += THREADS) {
        int g = t0 - 52 + i * 4;
        float4 v;
        if (g >= 0 && g + 3 < T_LEN) {
            v = *(const float4*)(xb + g);
        } else {
            v.x = (g + 0 >= 0 && g + 0 < T_LEN) ? xb[g + 0] : 0.0f;
            v.y = (g + 1 >= 0 && g + 1 < T_LEN) ? xb[g + 1] : 0.0f;
            v.z = (g + 2 >= 0 && g + 2 < T_LEN) ? xb[g + 2] : 0.0f;
            v.w = (g + 3 >= 0 && g + 3 < T_LEN) ? xb[g + 3] : 0.0f;
        }
        if (i * 4 < SX_LEN) *(float4*)&sxA[i * 4] = v;
        int j = i * 4 - 1;                       // sxB[j] = sxA[j+1]
        if (j >= 0) sxB[j] = v.x;
        sxB[j + 1] = v.y; sxB[j + 2] = v.z; sxB[j + 3] = v.w;
    }
    // --- stage reversed coeffs + diff: sc[f*100+2j] = bL[49-j], +1 = bR-bL ---
    for (int i = tid; i < FPB * TAPS; i += THREADS) {
        int f  = i / TAPS;
        int j  = i - f * TAPS;
        int fg = f0 + f;
        if (fg < N_FRAMES) {
            int k = ORD - j;
            float bl = bbp[fg * TAPS + k];
            int f1 = (fg + 1 < N_FRAMES) ? fg + 1 : N_FRAMES - 1;
            float br = bbp[f1 * TAPS + k];
            sc[f * (2 * TAPS) + 2 * j]     = bl;
            sc[f * (2 * TAPS) + 2 * j + 1] = br - bl;
        }
    }
    __syncthreads();

    const int fi  = tid / TPF;            // frame within block
    const int sub = tid - fi * TPF;
    const int p0  = sub * R;              // phase of first sample in frame
    const int s   = fi * FPERIOD + p0;    // first sample offset in block (mult of 8)
    const bool active = (f0 + fi) < N_FRAMES;

    // Output pair m2 covers samples (s+2m2, s+2m2+1).
    // Tap j operand pair starts at sxA-index q = s+2m2+j+3.
    //  j even -> q odd  -> read sxB[q-1] (8B aligned)
    //  j odd  -> q even -> read sxA[q]   (8B aligned)
    ull A0_0 = 0, A0_1 = 0, A0_2 = 0, A0_3 = 0;   // sum x*bL (packed pairs)
    ull A1_0 = 0, A1_1 = 0, A1_2 = 0, A1_3 = 0;   // sum x*diff

    // initial windows (a = 0): WB at sxB[s+2+2m2], WA at sxA[s+4+2m2]
    ull wb0 = lds64(&sxB[s + 2]), wb1 = lds64(&sxB[s + 4]);
    ull wb2 = lds64(&sxB[s + 6]), wb3 = lds64(&sxB[s + 8]);
    ull wa0 = lds64(&sxA[s + 4]), wa1 = lds64(&sxA[s + 6]);
    ull wa2 = lds64(&sxA[s + 8]), wa3 = lds64(&sxA[s + 10]);

    const float4* cp = (const float4*)&sc[fi * (2 * TAPS)]; // (c,d,c,d) per 2 taps

    #pragma unroll
    for (int a = 0; a < TAPS / 2; a++) {          // taps j=2a, 2a+1
        float4 c = cp[a];
        ull cbE = pack2(c.x, c.x), cdE = pack2(c.y, c.y);
        ull cbO = pack2(c.z, c.z), cdO = pack2(c.w, c.w);

        A0_0 = fma2(wb0, cbE, A0_0);  A1_0 = fma2(wb0, cdE, A1_0);
        A0_1 = fma2(wb1, cbE, A0_1);  A1_1 = fma2(wb1, cdE, A1_1);
        A0_2 = fma2(wb2, cbE, A0_2);  A1_2 = fma2(wb2, cdE, A1_2);
        A0_3 = fma2(wb3, cbE, A0_3);  A1_3 = fma2(wb3, cdE, A1_3);

        A0_0 = fma2(wa0, cbO, A0_0);  A1_0 = fma2(wa0, cdO, A1_0);
        A0_1 = fma2(wa1, cbO, A0_1);  A1_1 = fma2(wa1, cdO, A1_1);
        A0_2 = fma2(wa2, cbO, A0_2);  A1_2 = fma2(wa2, cdO, A1_2);
        A0_3 = fma2(wa3, cbO, A0_3);  A1_3 = fma2(wa3, cdO, A1_3);

        if (a < TAPS / 2 - 1) {
            wb0 = wb1; wb1 = wb2; wb2 = wb3; wb3 = lds64(&sxB[s + 2 * a + 10]);
            wa0 = wa1; wa1 = wa2; wa2 = wa3; wa3 = lds64(&sxA[s + 2 * a + 12]);
        }
    }

    if (active) {
        const float inv = 1.0f / FPERIOD;
        ull wt0 = pack2((float)(p0 + 0) * inv, (float)(p0 + 1) * inv);
        ull wt1 = pack2((float)(p0 + 2) * inv, (float)(p0 + 3) * inv);
        ull wt2 = pack2((float)(p0 + 4) * inv, (float)(p0 + 5) * inv);
        ull wt3 = pack2((float)(p0 + 6) * inv, (float)(p0 + 7) * inv);
        ull r0 = fma2(wt0, A1_0, A0_0);
        ull r1 = fma2(wt1, A1_1, A0_1);
        ull r2 = fma2(wt2, A1_2, A0_2);
        ull r3 = fma2(wt3, A1_3, A0_3);
        float* yo = y + (size_t)bb * T_LEN + t0 + s;   // 32B aligned
        ulonglong2 v0; v0.x = r0; v0.y = r1;
        ulonglong2 v1; v1.x = r2; v1.y = r3;
        *(ulonglong2*)yo       = v0;
        *((ulonglong2*)yo + 1) = v1;
    }
}

extern "C" void kernel_launch(void* const* d_in, const int* in_sizes, int n_in,
                              void* d_out, int out_size)
{
    const float* x = (const float*)d_in[0];
    const float* b = (const float*)d_in[1];
    if (in_sizes[0] != BATCH * T_LEN) {   // defensive input-order check
        const float* t = x; x = b; b = t;
    }
    dim3 grid(GRIDX, BATCH);              // 188 x 8
    azdf_kernel<<<grid, THREADS>>>(x, b, (float*)d_out);
}

// round 8
// speedup vs baseline: 1.0345x; 1.0345x over previous
#include <cuda_runtime.h>

// Time-varying FIR via packed fma.rn.f32x2 (Blackwell FFMA2), two-accumulator
// split y = A0 + w*A1. Coefficients pre-duplicated in shared as (c,c,d,d)
// float4 so the main loop needs zero register packing. Even/odd tap parity is
// handled by two shared x images offset by one float, keeping every 64-bit
// window load 8B-aligned.

#define BATCH     8
#define N_FRAMES  3000
#define FPERIOD   80
#define T_LEN     (N_FRAMES * FPERIOD)   // 240000
#define TAPS      50
#define ORD       49

#define FPB       8                      // frames per block (divides 3000)
#define SPB       (FPB * FPERIOD)        // 640
#define R         4                      // samples per thread (2 packed pairs)
#define TPF       (FPERIOD / R)          // 20 threads per frame
#define THREADS   (FPB * TPF)            // 160 = 5 warps

#define SX_LEN    704                    // 52 (left pad) + 640 + 12 spare

typedef unsigned long long ull;

__device__ __forceinline__ ull fma2(ull a, ull b, ull c) {
    ull d;
    asm("fma.rn.f32x2 %0, %1, %2, %3;" : "=l"(d) : "l"(a), "l"(b), "l"(c));
    return d;
}
__device__ __forceinline__ ull pack2(float lo, float hi) {
    ull d;
    asm("mov.b64 %0, {%1, %2};" : "=l"(d) : "f"(lo), "f"(hi));
    return d;
}
__device__ __forceinline__ ull lds64(const float* p) {
    return *(const ull*)p;               // 8B-aligned by construction
}

__global__ __launch_bounds__(THREADS)
void azdf_kernel(const float* __restrict__ x,
                 const float* __restrict__ b,
                 float* __restrict__ y)
{
    __shared__ __align__(16) float sxA[SX_LEN];        // sxA[i] = x[t0-52+i]
    __shared__ __align__(16) float sxB[SX_LEN];        // sxB[i] = x[t0-51+i]
    __shared__ __align__(16) float4 sc4[FPB * TAPS];   // (c49,c49,d49,d49) per tap

    const int tid = threadIdx.x;
    const int bb  = blockIdx.y;
    const int f0  = blockIdx.x * FPB;
    const int t0  = f0 * FPERIOD;

    const float* xb  = x + (size_t)bb * T_LEN;
    const float* bbp = b + (size_t)bb * N_FRAMES * TAPS;

    // --- stage both x images (float4 global loads, edge-guarded) ---
    for (int i4 = tid * 4; i4 < SX_LEN; i4 += THREADS * 4) {
        int g = t0 - 52 + i4;
        float4 v;
        if (g >= 0 && g + 3 < T_LEN) {
            v = *(const float4*)(xb + g);
        } else {
            v.x = (g + 0 >= 0 && g + 0 < T_LEN) ? xb[g + 0] : 0.0f;
            v.y = (g + 1 >= 0 && g + 1 < T_LEN) ? xb[g + 1] : 0.0f;
            v.z = (g + 2 >= 0 && g + 2 < T_LEN) ? xb[g + 2] : 0.0f;
            v.w = (g + 3 >= 0 && g + 3 < T_LEN) ? xb[g + 3] : 0.0f;
        }
        *(float4*)&sxA[i4] = v;
        if (i4 > 0) sxB[i4 - 1] = v.x;         // sxB[i] = sxA[i+1]
        sxB[i4]     = v.y;
        sxB[i4 + 1] = v.z;
        sxB[i4 + 2] = v.w;
    }
    // --- stage reversed coeffs pre-duplicated: sc4[f][j] = (bL,bL,d,d), j=49-k ---
    for (int i = tid; i < FPB * TAPS; i += THREADS) {
        int f = i / TAPS;
        int j = i - f * TAPS;
        int k = ORD - j;
        float bl = bbp[(f0 + f) * TAPS + k];
        int f1 = f0 + f + 1;
        if (f1 > N_FRAMES - 1) f1 = N_FRAMES - 1;
        float br = bbp[f1 * TAPS + k];
        float4 q;
        q.x = bl; q.y = bl; q.z = br - bl; q.w = br - bl;
        sc4[f * TAPS + j] = q;
    }
    __syncthreads();

    const int fi  = tid / TPF;            // frame within block
    const int sub = tid - fi * TPF;       // thread within frame
    const int p0  = sub * R;              // phase of first sample in frame
    const int s   = fi * FPERIOD + p0;    // first sample offset (multiple of 4)

    // Output pair m2 in {0,1} covers samples (s+2m2, s+2m2+1).
    // Tap j pair starts at sxA-index q = s + 2m2 + j + 3:
    //   j even -> q odd  -> sxB[q-1] (aligned);  j odd -> q even -> sxA[q].
    ull A00 = 0, A01 = 0;                 // sum x*bL, pairs 0/1
    ull A10 = 0, A11 = 0;                 // sum x*diff

    ull wb0 = lds64(&sxB[s + 2]), wb1 = lds64(&sxB[s + 4]);
    ull wa0 = lds64(&sxA[s + 4]), wa1 = lds64(&sxA[s + 6]);

    const ulonglong2* cp = (const ulonglong2*)(sc4 + fi * TAPS);

    #pragma unroll
    for (int a = 0; a < TAPS / 2; a++) {          // taps j = 2a, 2a+1
        ulonglong2 ce = cp[2 * a];                // .x=(c,c) .y=(d,d) even tap
        ulonglong2 co = cp[2 * a + 1];            // odd tap

        A00 = fma2(wb0, ce.x, A00);  A10 = fma2(wb0, ce.y, A10);
        A01 = fma2(wb1, ce.x, A01);  A11 = fma2(wb1, ce.y, A11);
        A00 = fma2(wa0, co.x, A00);  A10 = fma2(wa0, co.y, A10);
        A01 = fma2(wa1, co.x, A01);  A11 = fma2(wa1, co.y, A11);

        if (a < TAPS / 2 - 1) {
            wb0 = wb1; wb1 = lds64(&sxB[s + 6 + 2 * a]);
            wa0 = wa1; wa1 = lds64(&sxA[s + 8 + 2 * a]);
        }
    }

    // epilogue: y = A0 + (phase/80)*A1 ; one 16B store
    const float inv = 1.0f / FPERIOD;
    ull wt0 = pack2((float)(p0 + 0) * inv, (float)(p0 + 1) * inv);
    ull wt1 = pack2((float)(p0 + 2) * inv, (float)(p0 + 3) * inv);
    ulonglong2 r;
    r.x = fma2(wt0, A10, A00);
    r.y = fma2(wt1, A11, A01);
    *(ulonglong2*)(y + (size_t)bb * T_LEN + t0 + s) = r;
}

extern "C" void kernel_launch(void* const* d_in, const int* in_sizes, int n_in,
                              void* d_out, int out_size)
{
    const float* x = (const float*)d_in[0];
    const float* b = (const float*)d_in[1];
    if (in_sizes[0] != BATCH * T_LEN) {   // defensive input-order check
        const float* t = x; x = b; b = t;
    }
    dim3 grid(N_FRAMES / FPB, BATCH);     // 375 x 8 = 3000 blocks
    azdf_kernel<<<grid, THREADS>>>(x, b, (float*)d_out);
}

// round 9
// speedup vs baseline: 1.1366x; 1.0987x over previous
#include <cuda_runtime.h>

// Time-varying FIR via packed fma.rn.f32x2 (Blackwell FFMA2).
//   y[t] = sum_k x[t-k]*(bL[n][k] + w*(bR[n][k]-bL[n][k])), n=t/80, w=(t%80)/80
// Two-accumulator split y = A0 + w*A1, outputs packed in pairs.
// R=10 samples/thread so each coefficient LDS.128 feeds 20 FFMA2 (LDS pipe was
// the R8 bottleneck at L1=71%). Coefficients pre-duplicated (c,c,d,d) in smem
// -> no register packing. Even/odd tap parity via two x images offset by one
// float so every 64-bit window load is 8B-aligned.

#define BATCH     8
#define N_FRAMES  3000
#define FPERIOD   80
#define T_LEN     (N_FRAMES * FPERIOD)   // 240000
#define TAPS      50
#define ORD       49

#define FPB       12                     // frames per block (3000/12 = 250)
#define SPB       (FPB * FPERIOD)        // 960 samples per block
#define R         10                     // samples per thread (5 packed pairs)
#define TPF       (FPERIOD / R)          // 8 threads per frame
#define THREADS   (FPB * TPF)            // 96 = 3 warps

#define SX_LEN    1024                   // 52 left pad + 960 + spare (float4 staged)

typedef unsigned long long ull;

__device__ __forceinline__ ull fma2(ull a, ull b, ull c) {
    ull d;
    asm("fma.rn.f32x2 %0, %1, %2, %3;" : "=l"(d) : "l"(a), "l"(b), "l"(c));
    return d;
}
__device__ __forceinline__ ull pack2(float lo, float hi) {
    ull d;
    asm("mov.b64 %0, {%1, %2};" : "=l"(d) : "f"(lo), "f"(hi));
    return d;
}
__device__ __forceinline__ ull lds64(const float* p) {
    return *(const ull*)p;               // 8B-aligned by construction
}

__global__ __launch_bounds__(THREADS)
void azdf_kernel(const float* __restrict__ x,
                 const float* __restrict__ b,
                 float* __restrict__ y)
{
    __shared__ __align__(16) float sxA[SX_LEN];        // sxA[i] = x[t0-52+i]
    __shared__ __align__(16) float sxB[SX_LEN];        // sxB[i] = x[t0-51+i]
    __shared__ __align__(16) float4 sc4[FPB * TAPS];   // (c49,c49,d49,d49) per tap

    const int tid = threadIdx.x;
    const int bb  = blockIdx.y;
    const int f0  = blockIdx.x * FPB;
    const int t0  = f0 * FPERIOD;

    const float* xb  = x + (size_t)bb * T_LEN;
    const float* bbp = b + (size_t)bb * N_FRAMES * TAPS;

    // --- stage both x images (float4 global loads, edge-guarded) ---
    for (int i4 = tid * 4; i4 < SX_LEN; i4 += THREADS * 4) {
        int g = t0 - 52 + i4;
        float4 v;
        if (g >= 0 && g + 3 < T_LEN) {
            v = *(const float4*)(xb + g);
        } else {
            v.x = (g + 0 >= 0 && g + 0 < T_LEN) ? xb[g + 0] : 0.0f;
            v.y = (g + 1 >= 0 && g + 1 < T_LEN) ? xb[g + 1] : 0.0f;
            v.z = (g + 2 >= 0 && g + 2 < T_LEN) ? xb[g + 2] : 0.0f;
            v.w = (g + 3 >= 0 && g + 3 < T_LEN) ? xb[g + 3] : 0.0f;
        }
        *(float4*)&sxA[i4] = v;
        if (i4 > 0) sxB[i4 - 1] = v.x;          // sxB[i] = sxA[i+1]
        sxB[i4]     = v.y;
        sxB[i4 + 1] = v.z;
        if (i4 + 2 < SX_LEN) sxB[i4 + 2] = v.w;
    }
    // --- stage reversed coeffs duplicated: sc4[f][j] = (bL,bL,d,d), j = 49-k ---
    for (int i = tid; i < FPB * TAPS; i += THREADS) {
        int f = i / TAPS;
        int j = i - f * TAPS;
        int k = ORD - j;
        float bl = bbp[(f0 + f) * TAPS + k];
        int f1 = f0 + f + 1;
        if (f1 > N_FRAMES - 1) f1 = N_FRAMES - 1;
        float br = bbp[f1 * TAPS + k];
        float4 q;
        q.x = bl; q.y = bl; q.z = br - bl; q.w = br - bl;
        sc4[f * TAPS + j] = q;
    }
    __syncthreads();

    const int fi  = tid / TPF;            // frame within block
    const int sub = tid - fi * TPF;       // thread within frame
    const int p0  = sub * R;              // phase of first sample in frame (even)
    const int s   = fi * FPERIOD + p0;    // first sample offset in block (even)

    // Output pair m in {0..4} covers samples (s+2m, s+2m+1).
    // Tap j operand pair starts at sxA-index q = s + 2m + j + 3:
    //   j even -> q odd  -> sxB[q-1] (aligned);  j odd -> q even -> sxA[q].
    ull A00=0, A01=0, A02=0, A03=0, A04=0;    // sum x*bL  (packed pairs)
    ull A10=0, A11=0, A12=0, A13=0, A14=0;    // sum x*diff

    // initial windows at a=0: wb_m = sxB[s+2m+2], wa_m = sxA[s+2m+4]
    ull wb0 = lds64(&sxB[s + 2]),  wb1 = lds64(&sxB[s + 4]);
    ull wb2 = lds64(&sxB[s + 6]),  wb3 = lds64(&sxB[s + 8]);
    ull wb4 = lds64(&sxB[s + 10]);
    ull wa0 = lds64(&sxA[s + 4]),  wa1 = lds64(&sxA[s + 6]);
    ull wa2 = lds64(&sxA[s + 8]),  wa3 = lds64(&sxA[s + 10]);
    ull wa4 = lds64(&sxA[s + 12]);

    const ulonglong2* cp = (const ulonglong2*)(sc4 + fi * TAPS);

    #pragma unroll
    for (int a = 0; a < TAPS / 2; a++) {          // taps j = 2a, 2a+1
        ulonglong2 ce = cp[2 * a];                // .x=(c,c) .y=(d,d), even tap
        ulonglong2 co = cp[2 * a + 1];            // odd tap

        A00 = fma2(wb0, ce.x, A00);  A10 = fma2(wb0, ce.y, A10);
        A01 = fma2(wb1, ce.x, A01);  A11 = fma2(wb1, ce.y, A11);
        A02 = fma2(wb2, ce.x, A02);  A12 = fma2(wb2, ce.y, A12);
        A03 = fma2(wb3, ce.x, A03);  A13 = fma2(wb3, ce.y, A13);
        A04 = fma2(wb4, ce.x, A04);  A14 = fma2(wb4, ce.y, A14);

        A00 = fma2(wa0, co.x, A00);  A10 = fma2(wa0, co.y, A10);
        A01 = fma2(wa1, co.x, A01);  A11 = fma2(wa1, co.y, A11);
        A02 = fma2(wa2, co.x, A02);  A12 = fma2(wa2, co.y, A12);
        A03 = fma2(wa3, co.x, A03);  A13 = fma2(wa3, co.y, A13);
        A04 = fma2(wa4, co.x, A04);  A14 = fma2(wa4, co.y, A14);

        if (a < TAPS / 2 - 1) {
            wb0 = wb1; wb1 = wb2; wb2 = wb3; wb3 = wb4;
            wb4 = lds64(&sxB[s + 12 + 2 * a]);
            wa0 = wa1; wa1 = wa2; wa2 = wa3; wa3 = wa4;
            wa4 = lds64(&sxA[s + 14 + 2 * a]);
        }
    }

    // epilogue: y = A0 + (phase/80)*A1 ; five 8B stores (s*4B is 8B-aligned)
    const float inv = 1.0f / FPERIOD;
    ull* yo = (ull*)(y + (size_t)bb * T_LEN + t0 + s);
    yo[0] = fma2(pack2((float)(p0 + 0) * inv, (float)(p0 + 1) * inv), A10, A00);
    yo[1] = fma2(pack2((float)(p0 + 2) * inv, (float)(p0 + 3) * inv), A11, A01);
    yo[2] = fma2(pack2((float)(p0 + 4) * inv, (float)(p0 + 5) * inv), A12, A02);
    yo[3] = fma2(pack2((float)(p0 + 6) * inv, (float)(p0 + 7) * inv), A13, A03);
    yo[4] = fma2(pack2((float)(p0 + 8) * inv, (float)(p0 + 9) * inv), A14, A04);
}

extern "C" void kernel_launch(void* const* d_in, const int* in_sizes, int n_in,
                              void* d_out, int out_size)
{
    const float* x = (const float*)d_in[0];
    const float* b = (const float*)d_in[1];
    if (in_sizes[0] != BATCH * T_LEN) {   // defensive input-order check
        const float* t = x; x = b; b = t;
    }
    dim3 grid(N_FRAMES / FPB, BATCH);     // 250 x 8 = 2000 blocks
    azdf_kernel<<<grid, THREADS>>>(x, b, (float*)d_out);
}